// round 15
// baseline (speedup 1.0000x reference)
#include <cuda_runtime.h>
#include <cuda_fp16.h>
#include <cstdint>

// ---------------- scratch (static device globals; no allocation) ----------------
__device__ __half2 g_XS2[64*32*32*64];   // complex spectrum fp16, [b][i-32][h-32][w]
__device__ float  g_AB [32*64*32*64];    // |xs| fp32, [p][c][h-32][w]
__device__ float  g_Wt [32*32*64];       // filter*attention weight [i-32][h-32][w]
__device__ float  g_xsp[64*64*64];       // (1-mix)*conv result [b][h][w]

// ---------------- reference swizzle (epilogues only) ----------------
__device__ __forceinline__ int SWA(int r, int c){
    int k = ((r & 6) ^ ((r >> 3) & 7)) ^ (((r ^ (r >> 3)) & 1) << 3);
    return (r << 6) + (c ^ ((c >> 3) & 7) ^ k);
}

// ---------------- packed f32x2 helpers (Blackwell) ----------------
__device__ __forceinline__ float2 cadd(float2 a, float2 b){
    float2 r;
    asm("add.rn.f32x2 %0, %1, %2;"
        : "=l"(reinterpret_cast<uint64_t&>(r))
        : "l"(reinterpret_cast<const uint64_t&>(a)),
          "l"(reinterpret_cast<const uint64_t&>(b)));
    return r;
}
__device__ __forceinline__ float2 csub(float2 a, float2 b){
    float2 r;
    asm("sub.rn.f32x2 %0, %1, %2;"
        : "=l"(reinterpret_cast<uint64_t&>(r))
        : "l"(reinterpret_cast<const uint64_t&>(a)),
          "l"(reinterpret_cast<const uint64_t&>(b)));
    return r;
}
__device__ __forceinline__ float2 ffma2(float2 a, float2 b, float2 c){
    float2 r;
    asm("fma.rn.f32x2 %0, %1, %2, %3;"
        : "=l"(reinterpret_cast<uint64_t&>(r))
        : "l"(reinterpret_cast<const uint64_t&>(a)),
          "l"(reinterpret_cast<const uint64_t&>(b)),
          "l"(reinterpret_cast<const uint64_t&>(c)));
    return r;
}

__device__ __forceinline__ float2 cmul(float2 a, float2 b){
    return make_float2(fmaf(a.x, b.x, -a.y*b.y), fmaf(a.x, b.y, a.y*b.x));
}

template<int DIR>
__device__ __forceinline__ float2 mulJ(float2 t){
    return (DIR < 0) ? make_float2(t.y, -t.x) : make_float2(-t.y, t.x);
}

template<int DIR>
__device__ __forceinline__ void fft8(float2 v[8]){
    float2 e0=v[0], e1=v[2], e2=v[4], e3=v[6];
    float2 o0=v[1], o1=v[3], o2=v[5], o3=v[7];
    float2 t0=cadd(e0,e2), t1=csub(e0,e2), t2=cadd(e1,e3), t3=mulJ<DIR>(csub(e1,e3));
    float2 E0=cadd(t0,t2), E1=cadd(t1,t3), E2=csub(t0,t2), E3=csub(t1,t3);
    float2 u0=cadd(o0,o2), u1=csub(o0,o2), u2=cadd(o1,o3), u3=mulJ<DIR>(csub(o1,o3));
    float2 O0=cadd(u0,u2), O1=cadd(u1,u3), O2=csub(u0,u2), O3=csub(u1,u3);
    const float s = 0.70710678118654752f;
    const float2 w1v = make_float2( s, DIR < 0 ? -s : s);
    const float2 w3v = make_float2(-s, DIR < 0 ? -s : s);
    O1 = cmul(O1, w1v);
    O2 = mulJ<DIR>(O2);
    O3 = cmul(O3, w3v);
    v[0]=cadd(E0,O0); v[4]=csub(E0,O0);
    v[1]=cadd(E1,O1); v[5]=csub(E1,O1);
    v[2]=cadd(E2,O2); v[6]=csub(E2,O2);
    v[3]=cadd(E3,O3); v[7]=csub(E3,O3);
}

// Per-thread twiddles w8[c] = e^{DIR*2*pi*i*t*c/64}.
template<int DIR>
__device__ __forceinline__ void make_tw(float2 w8[8], int t){
    float sn, cs;
    sincospif((DIR < 0 ? -(float)t : (float)t) * (1.0f/32.0f), &sn, &cs);
    w8[0] = make_float2(1.0f, 0.0f);
    w8[1] = make_float2(cs, sn);
    #pragma unroll
    for (int c = 2; c < 8; c++) w8[c] = cmul(w8[c-1], w8[1]);
}

// Row stage-1 store (with twiddle), then remaining 3 FFT stages.
template<int DIR>
__device__ __forceinline__ void fft2d_from_rows(float2* S, float2 v[8],
                                                const float2 w8[8], int tid){
    const int t = tid & 7;
    const int line = tid >> 3;
    const int K  = ((line & 6) ^ ((line >> 3) & 7)) ^ (((line ^ (line >> 3)) & 1) << 3);
    char* Srow = (char*)S + (line << 9);
    const uint32_t TKB = (uint32_t)(t ^ K) << 3;
    const uint32_t UB  = (uint32_t)((t << 3) ^ t ^ K) << 3;
    // rows stage-1 store (twiddled)
    *(float2*)(Srow + (0u ^ TKB)) = v[0];
    #pragma unroll
    for (int c=1;c<8;c++)
        *(float2*)(Srow + ((uint32_t)(((c<<3)^c)<<3) ^ TKB)) = cmul(v[c], w8[c]);
    __syncwarp();
    // rows stage-2 (same line -> same warp)
    #pragma unroll
    for (int b=0;b<8;b++)
        v[b] = *(float2*)(Srow + (UB ^ (uint32_t)(b<<3)));
    fft8<DIR>(v);
    __syncwarp();
    #pragma unroll
    for (int d=0;d<8;d++)
        *(float2*)(Srow + ((uint32_t)(((d<<3)^d)<<3) ^ TKB)) = v[d];
    __syncthreads();            // transpose boundary (cross-warp)
    // columns
    const int L = line ^ ((line >> 3) & 7);
    const uint32_t MB = (uint32_t)(L ^ (t & 6) ^ ((t & 1) << 3)) << 3;
    const uint32_t NB = (uint32_t)(L ^ t ^ ((t & 1) << 3)) << 3;
    char* Sb = (char*)S;
    const uint32_t TB9  = (uint32_t)t << 9;
    const uint32_t TB12 = (uint32_t)t << 12;
    #pragma unroll
    for (int a=0;a<8;a++)
        v[a] = *(float2*)(Sb + (uint32_t)(a<<12) + TB9 + (MB ^ (uint32_t)((a ^ ((a&1)<<3))<<3)));
    fft8<DIR>(v);
    *(float2*)(Sb + TB9 + (MB ^ 0u)) = v[0];
    #pragma unroll
    for (int c=1;c<8;c++)
        *(float2*)(Sb + (uint32_t)(c<<12) + TB9 + (MB ^ (uint32_t)((c ^ ((c&1)<<3))<<3))) = cmul(v[c], w8[c]);
    __syncwarp();
    #pragma unroll
    for (int b=0;b<8;b++)
        v[b] = *(float2*)(Sb + TB12 + (uint32_t)(b<<9) + (NB ^ (uint32_t)((((b&6) ^ ((b&1)<<3)))<<3)));
    fft8<DIR>(v);
    __syncwarp();
    #pragma unroll
    for (int d=0;d<8;d++)
        *(float2*)(Sb + (uint32_t)(d<<12) + TB9 + (MB ^ (uint32_t)((d ^ ((d&1)<<3))<<3))) = v[d];
    __syncthreads();            // before cross-warp epilogue reads
}

__device__ __forceinline__ int band_idx(float f){
    return (int)floorf((f + 1.0f) * 0.5f * 64.0f);
}

// ---------------- kernel A: conv blocks (front) + forward FFT blocks ----------------
// __launch_bounds__(512,3): cap regs ~42 so 3 blocks/SM fit (was 2 via 56 regs).
__global__ __launch_bounds__(512, 3) void k_fwdconv(const float* __restrict__ x,
                                                    const float* __restrict__ fbs,
                                                    const float* __restrict__ cw,
                                                    const float* __restrict__ mixp){
    __shared__ float2 S[64*64];
    const int tid = threadIdx.x;

    if (blockIdx.x < 128){
        // ======== 3x3 spatial conv: direct gmem loads, channel pairs in f32x2 ========
        float2* cwS = S;                  // [32][9]
        const int b  = blockIdx.x >> 1;
        const int r0 = (blockIdx.x & 1) * 32;
        for (int k = tid; k < 288; k += 512){
            int cp = k / 9, t = k - cp*9;
            cwS[k] = make_float2(cw[(2*cp)*9 + t], cw[(2*cp+1)*9 + t]);
        }
        __syncthreads();
        const int r  = tid >> 4;          // 0..31
        const int w0 = (tid & 15) * 4;    // 0..60
        const bool mok = (w0 > 0), pok = (w0 < 60);
        float2 acc[4];
        #pragma unroll
        for (int l=0;l<4;l++) acc[l] = make_float2(0.f, 0.f);
        for (int cp = 0; cp < 32; cp++){
            const float* baseA = x + ((size_t)(b*64 + 2*cp) << 12);
            const float* baseB = baseA + 4096;
            float2 c9[9];
            #pragma unroll
            for (int q=0;q<9;q++) c9[q] = cwS[cp*9 + q];
            #pragma unroll
            for (int dy=0; dy<3; dy++){
                const int gr = r0 + r + dy - 1;
                if (gr >= 0 && gr < 64){
                    const float* rowA = baseA + gr*64;
                    const float* rowB = baseB + gr*64;
                    float4 a4 = *(const float4*)(rowA + w0);
                    float4 b4 = *(const float4*)(rowB + w0);
                    float am = mok ? rowA[w0-1] : 0.f;
                    float bm = mok ? rowB[w0-1] : 0.f;
                    float ap = pok ? rowA[w0+4] : 0.f;
                    float bp = pok ? rowB[w0+4] : 0.f;
                    float2 m1 = make_float2(am, bm);
                    float2 v0 = make_float2(a4.x, b4.x);
                    float2 v1 = make_float2(a4.y, b4.y);
                    float2 v2 = make_float2(a4.z, b4.z);
                    float2 v3 = make_float2(a4.w, b4.w);
                    float2 p4 = make_float2(ap, bp);
                    const float2* cr = &c9[dy*3];
                    acc[0] = ffma2(cr[0], m1, acc[0]); acc[0] = ffma2(cr[1], v0, acc[0]); acc[0] = ffma2(cr[2], v1, acc[0]);
                    acc[1] = ffma2(cr[0], v0, acc[1]); acc[1] = ffma2(cr[1], v1, acc[1]); acc[1] = ffma2(cr[2], v2, acc[1]);
                    acc[2] = ffma2(cr[0], v1, acc[2]); acc[2] = ffma2(cr[1], v2, acc[2]); acc[2] = ffma2(cr[2], v3, acc[2]);
                    acc[3] = ffma2(cr[0], v2, acc[3]); acc[3] = ffma2(cr[1], v3, acc[3]); acc[3] = ffma2(cr[2], p4, acc[3]);
                }
            }
        }
        const float c1 = 1.0f - mixp[0];
        float4 outv = make_float4(c1*(acc[0].x+acc[0].y), c1*(acc[1].x+acc[1].y),
                                  c1*(acc[2].x+acc[2].y), c1*(acc[3].x+acc[3].y));
        *(float4*)(g_xsp + b*4096 + (r0 + r)*64 + w0) = outv;
        return;
    }

    // ======== forward FFT ========
    const int bx = blockIdx.x - 128;      // 0..1535
    int pA, qA, pB, qB;
    bool magN, cA = false, cB = false;
    if (bx < 1024){                 // set1: q<32, pairs along p
        int q = bx & 31, m = bx >> 5;
        pA = 2*m;   pB = 2*m + 1;  qA = q; qB = q;
        magN = (pA < 32);
        const int i = q + 32;
        const int bA = (pA + 32) & 63, bB = (pB + 32) & 63;
        cA = (i >= band_idx(fbs[bA*2+0])) && (i < band_idx(fbs[bA*2+1]));
        cB = (i >= band_idx(fbs[bB*2+0])) && (i < band_idx(fbs[bB*2+1]));
        if (!magN && !cA && !cB) return;   // plane pair feeds nothing
    } else {                        // set2: p<32, q>=32, pairs along q (mag only)
        int idx = bx - 1024;
        int p = idx & 31, m = idx >> 5;
        pA = p; pB = p; qA = 32 + 2*m; qB = 33 + 2*m;
        magN = true;
    }
    const int t = tid & 7;
    const int line = tid >> 3;
    float2 w8[8];
    make_tw<-1>(w8, t);
    // row stage-1: direct gmem loads; sign = (-1)^(line+t) (cols step by 8)
    {
        const float sgn = ((line + t) & 1) ? -1.0f : 1.0f;
        const float* pa = x + ((size_t)(pA*64 + qA) << 12) + line*64 + t;
        const float* pb = x + ((size_t)(pB*64 + qB) << 12) + line*64 + t;
        float2 v[8];
        #pragma unroll
        for (int a=0;a<8;a++)
            v[a] = make_float2(pa[a*8]*sgn, pb[a*8]*sgn);
        fft8<-1>(v);
        fft2d_from_rows<-1>(S, v, w8, tid);
    }

    if (bx < 1024){
        const int bA = (pA + 32) & 63, bB = (pB + 32) & 63;
        __half2* dstA = g_XS2 + ((size_t)(bA*32 + qA) << 11);
        __half2* dstB = g_XS2 + ((size_t)(bB*32 + qB) << 11);
        float* magA = g_AB + ((size_t)(pA*64 + (qA + 32)) << 11);
        float* magB = g_AB + ((size_t)(pB*64 + (qB + 32)) << 11);
        for (int k = tid; k < 2048; k += 512){
            const int hh = 32 + (k >> 6);
            const int ww = k & 63;
            const int mh = 64 - hh;
            const int mw = (64 - ww) & 63;
            float2 z  = S[SWA(hh, ww)];
            float2 zp = S[SWA(mh, mw)];
            float2 fa = make_float2(0.5f*(z.x + zp.x), 0.5f*(z.y - zp.y));
            float2 fb = make_float2(0.5f*(z.y + zp.y), 0.5f*(zp.x - z.x));
            if (cA) dstA[k] = __floats2half2_rn(fa.x, fa.y);
            if (cB) dstB[k] = __floats2half2_rn(fb.x, fb.y);
            if (magN){
                magA[k] = sqrtf(fmaf(fa.x, fa.x, fa.y*fa.y));
                magB[k] = sqrtf(fmaf(fb.x, fb.x, fb.y*fb.y));
            }
        }
    } else {
        float* magA = g_AB + ((size_t)(pA*64 + (qA - 32)) << 11);
        float* magB = g_AB + ((size_t)(pB*64 + (qB - 32)) << 11);
        for (int k = tid; k < 2048; k += 512){
            const int hh = 32 + (k >> 6);
            const int ww = k & 63;
            const int mh = 64 - hh;
            const int mw = (64 - ww) & 63;
            float2 z  = S[SWA(hh, ww)];
            float2 zp = S[SWA(mh, mw)];
            float ax = 0.5f*(z.x + zp.x), ay = 0.5f*(z.y - zp.y);
            float bx2 = 0.5f*(z.y + zp.y), by = 0.5f*(zp.x - z.x);
            magA[k] = sqrtf(fmaf(ax, ax, ay*ay));
            magB[k] = sqrtf(fmaf(bx2, bx2, by*by));
        }
    }
}

// ---------------- kernel B: attention matvec + log-Gabor -> Wt ----------------
__global__ __launch_bounds__(256) void k_attn(const float* __restrict__ f0,
        const float* __restrict__ theta, const float* __restrict__ sigma,
        const float* __restrict__ theta0, const float* __restrict__ w1,
        const float* __restrict__ b1, const float* __restrict__ w2,
        const float* __restrict__ b2){
    __shared__ float sA[64*64];    // |xs| tile [c][w]
    __shared__ float sW[64*68];    // w1 transposed [c][o] (68-pad, float4-aligned); reused as h1 [o*65+w]
    __shared__ float sw2[3*64];
    const int io = blockIdx.x & 31, hp = blockIdx.x >> 5;
    const int i = io + 32, h = hp + 32;
    const int tid = threadIdx.x;

    // stage w1 transposed: sW[c*68 + o] = w1[o*64 + c]
    for (int k = tid; k < 4096; k += 256){
        int o = k >> 6, c = k & 63;
        sW[c*68 + o] = w1[k];
    }
    if (tid < 192) sw2[tid] = w2[tid];
    const float* base = g_AB + (((size_t)io*64) << 11) + ((size_t)hp << 6);
    for (int k = tid; k < 4096; k += 256){
        int c = k >> 6, w = k & 63;
        sA[c*64 + w] = base[((size_t)c << 11) + w];
    }
    __syncthreads();

    // h1 = relu(b1 + w1 @ |xs|): 4o x 4w per thread, float4 weight loads
    const int tw = tid & 15, to = tid >> 4;
    const int o0 = to*4, w0 = tw*4;
    float2 acc[4][2];
    #pragma unroll
    for (int j=0;j<4;j++){
        float bv = b1[o0+j];
        acc[j][0] = make_float2(bv, bv);
        acc[j][1] = make_float2(bv, bv);
    }
    for (int c=0;c<64;c++){
        float4 av = *(const float4*)&sA[c*64 + w0];
        float4 wv = *(const float4*)&sW[c*68 + o0];   // broadcast within half-warp
        float2 av01 = make_float2(av.x, av.y);
        float2 av23 = make_float2(av.z, av.w);
        float2 w0v = make_float2(wv.x, wv.x);
        float2 w1v = make_float2(wv.y, wv.y);
        float2 w2v = make_float2(wv.z, wv.z);
        float2 w3v = make_float2(wv.w, wv.w);
        acc[0][0] = ffma2(w0v, av01, acc[0][0]); acc[0][1] = ffma2(w0v, av23, acc[0][1]);
        acc[1][0] = ffma2(w1v, av01, acc[1][0]); acc[1][1] = ffma2(w1v, av23, acc[1][1]);
        acc[2][0] = ffma2(w2v, av01, acc[2][0]); acc[2][1] = ffma2(w2v, av23, acc[2][1]);
        acc[3][0] = ffma2(w3v, av01, acc[3][0]); acc[3][1] = ffma2(w3v, av23, acc[3][1]);
    }
    __syncthreads();
    // h1 -> sW reused as [o*65 + w]
    #pragma unroll
    for (int j=0;j<4;j++){
        sW[(o0+j)*65 + w0+0] = fmaxf(acc[j][0].x, 0.0f);
        sW[(o0+j)*65 + w0+1] = fmaxf(acc[j][0].y, 0.0f);
        sW[(o0+j)*65 + w0+2] = fmaxf(acc[j][1].x, 0.0f);
        sW[(o0+j)*65 + w0+3] = fmaxf(acc[j][1].y, 0.0f);
    }
    __syncthreads();

    // tail: 4 threads per w, shfl-reduced
    {
        const int w = tid >> 2, sub = tid & 3;
        float d0 = 0.f, d1 = 0.f, d2 = 0.f;
        const int ob = sub * 16;
        #pragma unroll
        for (int oo = 0; oo < 16; oo++){
            int o = ob + oo;
            float hv = sW[o*65 + w];
            d0 = fmaf(sw2[o],       hv, d0);
            d1 = fmaf(sw2[64 + o],  hv, d1);
            d2 = fmaf(sw2[128 + o], hv, d2);
        }
        #pragma unroll
        for (int off = 1; off < 4; off <<= 1){
            d0 += __shfl_xor_sync(0xffffffffu, d0, off);
            d1 += __shfl_xor_sync(0xffffffffu, d1, off);
            d2 += __shfl_xor_sync(0xffffffffu, d2, off);
        }
        if (sub == 0){
            float lg0 = d0 + b2[0], lg1 = d1 + b2[1], lg2 = d2 + b2[2];
            float mx = fmaxf(lg0, fmaxf(lg1, lg2));
            float e0 = expf(lg0-mx), e1 = expf(lg1-mx), e2 = expf(lg2-mx);
            float inv = 1.0f/(e0+e1+e2);
            float awv[3] = {e0*inv, e1*inv, e2*inv};
            float yy = 2.0f*(float)h/63.0f - 1.0f;
            float xx = 2.0f*(float)w/63.0f - 1.0f;
            float r2 = fmaf(xx, xx, fmaf(yy, yy, 1e-6f));
            float lr = 0.5f*logf(r2);
            float phi = atan2f(yy, xx);
            float wt = 0.0f;
            #pragma unroll
            for (int s3=0;s3<3;s3++){
                float lf0 = logf(f0[s3*64+i]);
                float ls  = logf(sigma[s3*64+i]);
                float d1v = lr - lf0;
                float g  = expf(-(d1v*d1v)/(2.0f*ls*ls));
                float d2v = phi - theta[s3*64+i];
                float t0v = theta0[s3*64+i];
                float ang = expf(-(d2v*d2v)/(2.0f*t0v*t0v));
                wt = fmaf(g*ang, awv[s3], wt);
            }
            g_Wt[(io*32 + hp)*64 + w] = wt;
        }
    }
}

// ---------------- kernel C: lean base-term copy for ALL planes ----------------
__global__ __launch_bounds__(256) void k_copy(float* __restrict__ out){
    const int bx = blockIdx.x;                   // (bo*64 + ioo)
    const float4* sp4 = (const float4*)(g_xsp + ((size_t)(bx >> 6) << 12));
    float4* o4 = (float4*)(out + ((size_t)bx << 12));
    const int tid = threadIdx.x;
    o4[tid]       = sp4[tid];
    o4[tid + 256] = sp4[tid + 256];
    o4[tid + 512] = sp4[tid + 512];
    o4[tid + 768] = sp4[tid + 768];
}

// ---------------- kernel D: active planes only: masked IFFT + mix (overwrite) ----------------
__global__ __launch_bounds__(512) void k_inv(const float* __restrict__ fbs,
        const float* __restrict__ mixp, float* __restrict__ out){
    const int bo = blockIdx.x >> 6, ioo = blockIdx.x & 63;
    const int b = (bo + 32) & 63, i = (ioo + 32) & 63;   // ifftshift of batch/channel dims
    const int sidx = band_idx(fbs[b*2+0]);               // in [32,64)
    const int eidx = band_idx(fbs[b*2+1]);
    if (i < sidx || i >= eidx) return;                   // inactive: k_copy wrote it

    __shared__ float2 S[64*64];
    const int tid = threadIdx.x;
    const float mix = mixp[0];
    float* o = out + ((size_t)blockIdx.x << 12);
    const float* sp = g_xsp + bo*4096;                   // already scaled by (1-mix)
    const int t = tid & 7;
    const int line = tid >> 3;
    float2 w8[8];
    make_tw<1>(w8, t);
    {
        float2 v[8];
        if (line >= sidx && line < eidx){
            const __half2* src = g_XS2 + ((size_t)(b*32 + (i-32)) << 11) + (line-32)*64 + t;
            const float*   wr  = g_Wt + ((i-32)*32 + (line-32))*64 + t;
            #pragma unroll
            for (int a=0;a<8;a++){
                float2 z = __half22float2(src[a*8]);
                float wv = wr[a*8];
                v[a] = make_float2(z.x*wv, z.y*wv);
            }
            fft8<1>(v);
        } else {
            #pragma unroll
            for (int a=0;a<8;a++) v[a] = make_float2(0.0f, 0.0f);
        }
        fft2d_from_rows<1>(S, v, w8, tid);
    }
    const float sc = mix * (1.0f/4096.0f);
    for (int k = tid; k < 4096; k += 512){
        int yy = k >> 6, xx = k & 63;
        float par = ((yy + xx) & 1) ? -sc : sc;          // ifftshift(h,w) modulation
        o[k] = fmaf(par, S[SWA(yy, xx)].x, sp[k]);
    }
}

// ---------------- launch ----------------
extern "C" void kernel_launch(void* const* d_in, const int* in_sizes, int n_in,
                              void* d_out, int out_size){
    (void)in_sizes; (void)n_in; (void)out_size;
    const float* x      = (const float*)d_in[0];
    const float* f0     = (const float*)d_in[1];
    const float* theta  = (const float*)d_in[2];
    const float* sigma  = (const float*)d_in[3];
    const float* theta0 = (const float*)d_in[4];
    const float* fbs    = (const float*)d_in[5];
    const float* mix    = (const float*)d_in[6];
    const float* w1     = (const float*)d_in[7];
    const float* b1     = (const float*)d_in[8];
    const float* w2     = (const float*)d_in[9];
    const float* b2     = (const float*)d_in[10];
    const float* cw     = (const float*)d_in[11];
    float* out = (float*)d_out;

    k_fwdconv<<<1664, 512>>>(x, fbs, cw, mix);
    k_copy<<<4096, 256>>>(out);
    k_attn<<<1024, 256>>>(f0, theta, sigma, theta0, w1, b1, w2, b2);
    k_inv<<<4096, 512>>>(fbs, mix, out);
}